// round 13
// baseline (speedup 1.0000x reference)
#include <cuda_runtime.h>

#define ALPHA 0.95f
#define NUM_CLASSES 32000
#define VEC4 (NUM_CLASSES / 4)      // 8000 float4 per row
#define THREADS 1024
#define PER_T 8                     // ceil(8000 / 1024)

__global__ __launch_bounds__(THREADS, 1)
void kd_scale_kernel(const float* __restrict__ logits,
                     const int* __restrict__ labels,   // int32 (JAX x64 disabled)
                     float* __restrict__ out)
{
    const int row = blockIdx.x;
    const int tid = threadIdx.x;

    const float4* __restrict__ in4  = (const float4*)(logits + (size_t)row * NUM_CLASSES);
    float4* __restrict__       out4 = (float4*)(out    + (size_t)row * NUM_CLASSES);

    const int label = __ldg(labels + row);
    const int lvec  = label >> 2;
    const int lcomp = label & 3;

    __shared__ float warpsum[THREADS / 32];
    __shared__ float bcast[2];
    __shared__ float t_sh;          // label element, exported by its owning thread

    // ---- Phase 1: load full row into registers (front-batched LDG.128), partial sum ----
    float4 v[PER_T];
    float partial = 0.0f;
#pragma unroll
    for (int k = 0; k < PER_T; k++) {
        const int idx = tid + k * THREADS;
        if (idx < VEC4) {
            v[k] = in4[idx];
            partial += (v[k].x + v[k].y) + (v[k].z + v[k].w);
            if (idx == lvec) t_sh = ((const float*)&v[k])[lcomp];  // exactly one thread
        }
    }

    // ---- Block reduction ----
#pragma unroll
    for (int o = 16; o; o >>= 1)
        partial += __shfl_xor_sync(0xFFFFFFFFu, partial, o);

    const int wid = tid >> 5;
    const int lid = tid & 31;
    if (lid == 0) warpsum[wid] = partial;
    __syncthreads();                 // orders t_sh and warpsum

    if (wid == 0) {
        float s = (lid < THREADS / 32) ? warpsum[lid] : 0.0f;
#pragma unroll
        for (int o = 16; o; o >>= 1)
            s += __shfl_xor_sync(0xFFFFFFFFu, s, o);
        if (lid == 0) {
            const float S  = s;
            const float t  = t_sh;   // no dependent global load on the critical path
            const float sc = ALPHA / (1.0f + S - 2.0f * t);
            bcast[0] = sc;
            bcast[1] = 1.0f - sc * S;   // corr
        }
    }
    __syncthreads();

    const float sc   = bcast[0];
    const float corr = bcast[1];

    // ---- Phase 2: scale from registers, write out (STG.128) ----
#pragma unroll
    for (int k = 0; k < PER_T; k++) {
        const int idx = tid + k * THREADS;
        if (idx < VEC4) {
            float4 r;
            r.x = sc * v[k].x;
            r.y = sc * v[k].y;
            r.z = sc * v[k].z;
            r.w = sc * v[k].w;
            if (idx == lvec) {
                ((float*)&r)[lcomp] += corr;
            }
            out4[idx] = r;
        }
    }
}

extern "C" void kernel_launch(void* const* d_in, const int* in_sizes, int n_in,
                              void* d_out, int out_size)
{
    const float* logits = (const float*)d_in[0];
    const int*   labels = (const int*)d_in[1];
    float*       out    = (float*)d_out;

    const int batch = in_sizes[1];   // labels element count == BATCH
    kd_scale_kernel<<<batch, THREADS>>>(logits, labels, out);
}

// round 14
// speedup vs baseline: 1.6549x; 1.6549x over previous
#include <cuda_runtime.h>

#define ALPHA 0.95f
#define NUM_CLASSES 32000
#define VEC4 (NUM_CLASSES / 4)      // 8000 float4 per row
#define THREADS 1024
#define PER_T 8                     // ceil(8000 / 1024)

__global__ __launch_bounds__(THREADS, 1)
void kd_scale_kernel(const float* __restrict__ logits,
                     const int* __restrict__ labels,   // int32 (JAX x64 disabled)
                     float* __restrict__ out)
{
    const int row = blockIdx.x;
    const int tid = threadIdx.x;

    const float4* __restrict__ in4  = (const float4*)(logits + (size_t)row * NUM_CLASSES);
    float4* __restrict__       out4 = (float4*)(out    + (size_t)row * NUM_CLASSES);

    const int label = __ldg(labels + row);
    const int lvec  = label >> 2;
    const int lcomp = label & 3;

    // ---- Phase 1: load full row into registers. No consumers of v[k] other
    // than the sum FADDs -> ptxas front-batches all 8 LDG.E.128 (MLP_p1 = 8).
    // Do NOT add any store/shuffle that reads v[k] inside this loop (R13 regression).
    float4 v[PER_T];
    float partial = 0.0f;
#pragma unroll
    for (int k = 0; k < PER_T; k++) {
        const int idx = tid + k * THREADS;
        if (idx < VEC4) {
            v[k] = in4[idx];
            partial += (v[k].x + v[k].y) + (v[k].z + v[k].w);
        }
    }

    // ---- Block reduction ----
#pragma unroll
    for (int o = 16; o; o >>= 1)
        partial += __shfl_xor_sync(0xFFFFFFFFu, partial, o);

    __shared__ float warpsum[THREADS / 32];
    __shared__ float bcast[2];
    const int wid = tid >> 5;
    const int lid = tid & 31;
    if (lid == 0) warpsum[wid] = partial;
    __syncthreads();

    if (wid == 0) {
        float s = (lid < THREADS / 32) ? warpsum[lid] : 0.0f;
#pragma unroll
        for (int o = 16; o; o >>= 1)
            s += __shfl_xor_sync(0xFFFFFFFFu, s, o);
        if (lid == 0) {
            const float S  = s;
            const float t  = __ldg(logits + (size_t)row * NUM_CLASSES + label);
            const float sc = ALPHA / (1.0f + S - 2.0f * t);
            bcast[0] = sc;
            bcast[1] = 1.0f - sc * S;   // corr
        }
    }
    __syncthreads();

    const float sc   = bcast[0];
    const float corr = bcast[1];

    // ---- Phase 2: scale from registers, write out (STG.128) ----
#pragma unroll
    for (int k = 0; k < PER_T; k++) {
        const int idx = tid + k * THREADS;
        if (idx < VEC4) {
            float4 r;
            r.x = sc * v[k].x;
            r.y = sc * v[k].y;
            r.z = sc * v[k].z;
            r.w = sc * v[k].w;
            if (idx == lvec) {
                ((float*)&r)[lcomp] += corr;
            }
            out4[idx] = r;
        }
    }
}

extern "C" void kernel_launch(void* const* d_in, const int* in_sizes, int n_in,
                              void* d_out, int out_size)
{
    const float* logits = (const float*)d_in[0];
    const int*   labels = (const int*)d_in[1];
    float*       out    = (float*)d_out;

    const int batch = in_sizes[1];   // labels element count == BATCH
    kd_scale_kernel<<<batch, THREADS>>>(logits, labels, out);
}